// round 3
// baseline (speedup 1.0000x reference)
#include <cuda_runtime.h>

#define BATCH 256
#define S 2048
#define V 100000
#define E 128

#define GRID 256
#define BLOCK 512
#define NCHUNK 4
#define CHUNK_V 25024   // multiple of 32 floats (128B lines don't span chunks)

// proj[v] = dot(emb[v], fc_w). __device__ scratch (no cudaMalloc allowed).
__device__ float g_proj[V];
__device__ unsigned int g_bar;   // grid barrier counter (monotonic within a launch)

__global__ void reset_kernel() { g_bar = 0u; }

__device__ __forceinline__ void grid_barrier(unsigned int target) {
    __threadfence();             // make this thread's g_proj stores GPU-visible
    __syncthreads();             // all block's stores fenced before the arrive
    if (threadIdx.x == 0) {
        atomicAdd(&g_bar, 1u);
        while (*((volatile unsigned int*)&g_bar) < target) { }
    }
    __syncthreads();
}

__global__ void __launch_bounds__(BLOCK, 2)
fused_kernel(const int* __restrict__ text, const int* __restrict__ lengths,
             const float* __restrict__ emb, const float* __restrict__ fc_w,
             const float* __restrict__ fc_b, float* __restrict__ out)
{
    __shared__ float sred[16];
    const int tid  = threadIdx.x;
    const int lane = tid & 31;
    const int warp = tid >> 5;
    const int b    = blockIdx.x;

    // ---- upfront: my 4 tokens (one int4), out-of-length forced to -1 ----
    const int len = lengths[b];
    int4 t = reinterpret_cast<const int4*>(text + (size_t)b * S)[tid];
    const int s = tid * 4;
    if (s + 0 >= len) t.x = -1;
    if (s + 1 >= len) t.y = -1;
    if (s + 2 >= len) t.z = -1;
    if (s + 3 >= len) t.w = -1;

    // proj work decomposition: global warp id, 8 vocab rows per warp-job.
    const int gw  = b * (BLOCK / 32) + warp;        // 0..4095
    const int q   = lane & 3;                        // quarter of a row (8 float4s)
    const int sub = lane >> 2;                       // row within 8-row job

    const float4* wp = reinterpret_cast<const float4*>(fc_w);
    float acc = 0.0f;

    #pragma unroll
    for (int c = 0; c < NCHUNK; c++) {
        const int lo = c * CHUNK_V;
        const int hi = min(V, lo + CHUNK_V);

        // ---- proj(c): stream emb rows [lo,hi), dot with fc_w ----
        for (int rb = lo + gw * 8; rb < hi; rb += GRID * (BLOCK / 32) * 8) {
            int r  = rb + sub;
            int rc = min(r, hi - 1);
            const float4* rp = reinterpret_cast<const float4*>(emb) + (size_t)rc * (E / 4);
            float d = 0.0f;
            #pragma unroll
            for (int g = 0; g < 2; g++) {
                float4 e0 = rp[q + (g * 4 + 0) * 4];
                float4 e1 = rp[q + (g * 4 + 1) * 4];
                float4 e2 = rp[q + (g * 4 + 2) * 4];
                float4 e3 = rp[q + (g * 4 + 3) * 4];
                float4 w0 = wp[q + (g * 4 + 0) * 4];
                float4 w1 = wp[q + (g * 4 + 1) * 4];
                float4 w2 = wp[q + (g * 4 + 2) * 4];
                float4 w3 = wp[q + (g * 4 + 3) * 4];
                d = fmaf(e0.x, w0.x, d); d = fmaf(e0.y, w0.y, d);
                d = fmaf(e0.z, w0.z, d); d = fmaf(e0.w, w0.w, d);
                d = fmaf(e1.x, w1.x, d); d = fmaf(e1.y, w1.y, d);
                d = fmaf(e1.z, w1.z, d); d = fmaf(e1.w, w1.w, d);
                d = fmaf(e2.x, w2.x, d); d = fmaf(e2.y, w2.y, d);
                d = fmaf(e2.z, w2.z, d); d = fmaf(e2.w, w2.w, d);
                d = fmaf(e3.x, w3.x, d); d = fmaf(e3.y, w3.y, d);
                d = fmaf(e3.z, w3.z, d); d = fmaf(e3.w, w3.w, d);
            }
            // reduce across the 4 lanes sharing this row (lanes stay converged)
            d += __shfl_xor_sync(0xffffffffu, d, 1);
            d += __shfl_xor_sync(0xffffffffu, d, 2);
            if (q == 0 && r < hi) g_proj[r] = d;
        }

        // ---- chip-wide: proj(c) done everywhere ----
        grid_barrier((unsigned int)(c + 1) * GRID);

        // ---- gather(c): my tokens in [lo,hi). Falls through into proj(c+1),
        //      so these wavefronts overlap the next chunk's DRAM streaming.
        const unsigned int span = (unsigned int)(hi - lo);
        if ((unsigned int)(t.x - lo) < span) acc += __ldcg(&g_proj[t.x]);
        if ((unsigned int)(t.y - lo) < span) acc += __ldcg(&g_proj[t.y]);
        if ((unsigned int)(t.z - lo) < span) acc += __ldcg(&g_proj[t.z]);
        if ((unsigned int)(t.w - lo) < span) acc += __ldcg(&g_proj[t.w]);
    }

    // ---- block reduce: 512 threads -> out[b] ----
    #pragma unroll
    for (int off = 16; off; off >>= 1)
        acc += __shfl_xor_sync(0xffffffffu, acc, off);
    if (lane == 0) sred[warp] = acc;
    __syncthreads();
    if (warp == 0) {
        float v = (lane < 16) ? sred[lane] : 0.0f;
        #pragma unroll
        for (int off = 8; off; off >>= 1)
            v += __shfl_xor_sync(0xffffffffu, v, off);
        if (lane == 0)
            out[b] = v / (float)len + fc_b[0];
    }
}

extern "C" void kernel_launch(void* const* d_in, const int* in_sizes, int n_in,
                              void* d_out, int out_size) {
    const int*   text    = (const int*)d_in[0];
    const int*   lengths = (const int*)d_in[1];
    const float* emb     = (const float*)d_in[2];
    const float* fc_w    = (const float*)d_in[3];
    const float* fc_b    = (const float*)d_in[4];
    float* out = (float*)d_out;

    reset_kernel<<<1, 1>>>();                       // zero barrier counter (graph replay safe)
    fused_kernel<<<GRID, BLOCK>>>(text, lengths, emb, fc_w, fc_b, out);
}

// round 4
// speedup vs baseline: 1.4341x; 1.4341x over previous
#include <cuda_runtime.h>

#define B 256
#define S 2048
#define V 100000
#define E 128

// proj[v] = dot(emb[v], fc_w). __device__ scratch (no cudaMalloc allowed).
__device__ float g_proj[V];
__device__ float g_part[B * 4];   // 4 partial sums per batch row

// Kernel 1: each warp handles 8 vocab rows. Lane l owns row (l>>2), quarter
// q=(l&3): 8 independent float4 loads (MLP=8/lane), FMA vs preloaded fc_w,
// 2-shuffle reduce across the 4 lanes sharing a row. HBM-streaming bound.
__global__ void __launch_bounds__(256) proj_kernel(const float* __restrict__ emb,
                                                   const float* __restrict__ fc_w) {
    int lane = threadIdx.x & 31;
    int warp = threadIdx.x >> 5;
    int q = lane & 3;

    float4 w[8];
    #pragma unroll
    for (int j = 0; j < 8; j++)
        w[j] = reinterpret_cast<const float4*>(fc_w)[q + j * 4];

    int row = blockIdx.x * 64 + warp * 8 + (lane >> 2);
    bool valid = (row < V);
    int rowc = valid ? row : (V - 1);   // clamp: keep lanes converged for shfl

    const float4* rp = reinterpret_cast<const float4*>(emb + (size_t)rowc * E);
    float4 e[8];
    #pragma unroll
    for (int j = 0; j < 8; j++)
        e[j] = rp[q + j * 4];

    float acc = 0.0f;
    #pragma unroll
    for (int j = 0; j < 8; j++) {
        acc = fmaf(e[j].x, w[j].x, acc);
        acc = fmaf(e[j].y, w[j].y, acc);
        acc = fmaf(e[j].z, w[j].z, acc);
        acc = fmaf(e[j].w, w[j].w, acc);
    }
    acc += __shfl_xor_sync(0xffffffffu, acc, 1);
    acc += __shfl_xor_sync(0xffffffffu, acc, 2);
    if (valid && q == 0) g_proj[row] = acc;
}

// Kernel 2: 1024 blocks x 128 threads. Block (b, h) handles tokens
// [h*512, h*512+512) of batch row b: one int4 (4 tokens) per thread, a single
// round of independent L2/L1 gathers, block-reduce to a partial.
// 1024 blocks over 148 SMs -> near-perfect wave balance (~6.9/SM).
__global__ void __launch_bounds__(128) pool_partial_kernel(const int* __restrict__ text,
                                                           const int* __restrict__ lengths) {
    __shared__ float sred[4];
    int bid = blockIdx.x;
    int b = bid >> 2;
    int h = bid & 3;
    int tid = threadIdx.x;
    int len = lengths[b];

    int base = h * 512;                 // token offset within the row
    int4 t = reinterpret_cast<const int4*>(text + (size_t)b * S + base)[tid];
    int s = base + tid * 4;
    float acc = 0.0f;
    if (s + 0 < len) acc += g_proj[t.x];
    if (s + 1 < len) acc += g_proj[t.y];
    if (s + 2 < len) acc += g_proj[t.z];
    if (s + 3 < len) acc += g_proj[t.w];

    #pragma unroll
    for (int off = 16; off; off >>= 1)
        acc += __shfl_xor_sync(0xffffffffu, acc, off);
    int lane = tid & 31, warp = tid >> 5;
    if (lane == 0) sred[warp] = acc;
    __syncthreads();
    if (tid == 0)
        g_part[bid] = sred[0] + sred[1] + sred[2] + sred[3];
}

// Kernel 3: trivial finalize — combine 4 partials, divide by length, add bias.
__global__ void __launch_bounds__(256) finalize_kernel(const int* __restrict__ lengths,
                                                       const float* __restrict__ fc_b,
                                                       float* __restrict__ out) {
    int b = threadIdx.x;
    float v = g_part[b * 4 + 0] + g_part[b * 4 + 1] + g_part[b * 4 + 2] + g_part[b * 4 + 3];
    out[b] = v / (float)lengths[b] + fc_b[0];
}

extern "C" void kernel_launch(void* const* d_in, const int* in_sizes, int n_in,
                              void* d_out, int out_size) {
    const int*   text    = (const int*)d_in[0];
    const int*   lengths = (const int*)d_in[1];
    const float* emb     = (const float*)d_in[2];
    const float* fc_w    = (const float*)d_in[3];
    const float* fc_b    = (const float*)d_in[4];
    float* out = (float*)d_out;

    proj_kernel<<<(V + 63) / 64, 256>>>(emb, fc_w);
    pool_partial_kernel<<<B * 4, 128>>>(text, lengths);
    finalize_kernel<<<1, B>>>(lengths, fc_b, out);
}